// round 17
// baseline (speedup 1.0000x reference)
#include <cuda_runtime.h>
#include <cstdint>

// CRF loss: mean_b( logZ_b - gold_b )
// Forward recurrence e_t = diag(h_t) M e_{t-1} is a product of POSITIVE
// matrices -> Hilbert contraction: direction forgets its start geometrically
// (lambda2/lambda1 ~ 0.46/step). Sequences split into CHUNK-step chunks; each
// chunk warp runs WARM warm-up steps from a uniform vector, then its real
// steps, accumulating the telescoping log-magnitude gain
//   delta_c = off*ln2 + log nu(e_out) - log nu(e_in),  nu(x) = sum_n x[n].
// WARM=32 -> boundary error ~2e-11 (measured rel_err with WARM=96 was
// bit-identical to exact). Gold score folded into the last-chunk warp of
// each batch -> grid fits in ONE wave (<=1036 blocks @ 72 regs).
// Step body: smem exchange (1 STS + 8 LDS.128) + 15 packed f32x2 FMAs;
// renorm every 4 steps via shfl, exact via integer 'off'.

#define KSTATES   32
#define START_IDX 30
#define STOP_IDX  31
#define FULLMASK  0xffffffffu
#define LN2       0.6931471805599453f
#define CHUNK     256
#define WARM      32

__device__ float    g_chunk[8192];    // per-(batch,chunk) contributions
__device__ float    g_gold[4096];     // per-batch gold scores
__device__ unsigned g_count;          // zero-init; reset by last block

// s[lane] = sum_{p=0..29} expM[lane][p] * e[p], e gathered from smem.
// (p=30: e[START]=0 always here; p=31: column STOP of M is 0.)
__device__ __forceinline__ float crf_dot_smem(const unsigned long long* __restrict__ Mp,
                                              unsigned eaddr)
{
    unsigned long long ev[16];
#pragma unroll
    for (int q = 0; q < 8; q++) {
        asm volatile("ld.shared.v2.u64 {%0,%1}, [%2];"
                     : "=l"(ev[2 * q]), "=l"(ev[2 * q + 1])
                     : "r"(eaddr + 16u * q));
    }
    unsigned long long a0 = 0ull, a1 = 0ull, a2 = 0ull, a3 = 0ull;
#pragma unroll
    for (int i = 0; i < 12; i += 4) {
        asm("fma.rn.f32x2 %0, %1, %2, %0;" : "+l"(a0) : "l"(Mp[i    ]), "l"(ev[i    ]));
        asm("fma.rn.f32x2 %0, %1, %2, %0;" : "+l"(a1) : "l"(Mp[i + 1]), "l"(ev[i + 1]));
        asm("fma.rn.f32x2 %0, %1, %2, %0;" : "+l"(a2) : "l"(Mp[i + 2]), "l"(ev[i + 2]));
        asm("fma.rn.f32x2 %0, %1, %2, %0;" : "+l"(a3) : "l"(Mp[i + 3]), "l"(ev[i + 3]));
    }
    asm("fma.rn.f32x2 %0, %1, %2, %0;" : "+l"(a0) : "l"(Mp[12]), "l"(ev[12]));
    asm("fma.rn.f32x2 %0, %1, %2, %0;" : "+l"(a1) : "l"(Mp[13]), "l"(ev[13]));
    asm("fma.rn.f32x2 %0, %1, %2, %0;" : "+l"(a2) : "l"(Mp[14]), "l"(ev[14]));

    unsigned long long s01, s2;
    asm("add.rn.f32x2 %0, %1, %2;" : "=l"(s01) : "l"(a0),  "l"(a1));
    asm("add.rn.f32x2 %0, %1, %2;" : "=l"(s2)  : "l"(a2),  "l"(s01));
    asm("add.rn.f32x2 %0, %1, %2;" : "=l"(s2)  : "l"(a3),  "l"(s2));
    float lo, hi;
    asm("mov.b64 {%0, %1}, %2;" : "=f"(lo), "=f"(hi) : "l"(s2));
    return lo + hi;
}

__device__ __forceinline__ void crf_store_e(unsigned eaddr, int lane, float e)
{
    asm volatile("st.shared.f32 [%0], %1;"
                 :: "r"(eaddr + 4u * (unsigned)lane), "f"(e));
}

// 2^-k from e[0]'s exponent (register copy via shfl), k accumulated into off.
__device__ __forceinline__ float crf_renorm(float e, int& off)
{
    float c  = __shfl_sync(FULLMASK, e, 0);
    int   ie = (int)((__float_as_uint(c) >> 23) & 0xFF);
    ie = (ie == 0) ? 127 : ie;
    off += ie - 127;
    return __uint_as_float((unsigned)(254 - ie) << 23);
}

// Run `count` recurrence steps for times tbase..tbase+count-1.
// Prefetch clamped to lenm1 (valid memory; clamped values unused).
__device__ __forceinline__ void crf_run(const unsigned long long* __restrict__ Mp,
                                        unsigned eaddr, int lane,
                                        const float* __restrict__ fb,
                                        int tbase, int count, int lenm1,
                                        float& e, int& off)
{
    float fbuf[8];
#pragma unroll
    for (int i = 0; i < 8; i++) {
        int tt = tbase + i; tt = (tt < lenm1) ? tt : lenm1;
        fbuf[i] = fb[(size_t)tt * KSTATES];
    }
    const int s8 = count & ~7;
    for (int q = 0; q < s8; q += 8) {
#pragma unroll
        for (int j = 0; j < 8; j++) {
            float h = __expf(fbuf[j]);             // MUFU, off-path
            if ((j & 3) == 0)                      // renorm every 4 steps
                h *= crf_renorm(e, off);
            float s = crf_dot_smem(Mp, eaddr);
            e = s * h;
            crf_store_e(eaddr, lane, e);
            int tt = tbase + q + 8 + j; tt = (tt < lenm1) ? tt : lenm1;
            fbuf[j] = fb[(size_t)tt * KSTATES];
        }
    }
    for (int s = s8; s < count; s++) {             // <=7 step tail
        float h = __expf(fbuf[s - s8]) * crf_renorm(e, off);
        float sv = crf_dot_smem(Mp, eaddr);
        e = sv * h;
        crf_store_e(eaddr, lane, e);
    }
}

__device__ __forceinline__ float warp_sum(float v)
{
#pragma unroll
    for (int d = 16; d; d >>= 1)
        v += __shfl_xor_sync(FULLMASK, v, d);
    return v;
}

__global__ void __launch_bounds__(128)
crf_kernel(const float* __restrict__ feats,
           const float* __restrict__ trans,
           const int*   __restrict__ tags,
           const int*   __restrict__ lens,
           float* __restrict__ out,
           int B, int T, int nch)
{
    __shared__ __align__(16) float sh_e[4][KSTATES];
    const int tid  = threadIdx.x;
    const int wid  = tid >> 5;
    const int lane = tid & 31;

    const int id = blockIdx.x * 4 + wid;            // (batch, chunk) flat id
    if (id < B * nch) {
        const int b   = id / nch;
        const int c   = id % nch;
        const int len = lens[b];
        const int t0  = c * CHUNK;

        // ---------- forward chunk ----------
        if (c > 0 && t0 >= len) {
            if (lane == 0) g_chunk[id] = 0.0f;      // inactive chunk
        } else {
            const unsigned eaddr =
                (unsigned)__cvta_generic_to_shared(&sh_e[wid][0]);

            // Packed expM row: Mp[q] = (expM[lane][2q], expM[lane][2q+1]).
            // exp(-10000) -> exactly 0 (row START, column STOP).
            unsigned long long Mp[15];
#pragma unroll
            for (int q = 0; q < 15; q++) {
                float m0 = __expf(trans[lane * KSTATES + 2 * q]);
                float m1 = __expf(trans[lane * KSTATES + 2 * q + 1]);
                asm("mov.b64 %0, {%1, %2};" : "=l"(Mp[q]) : "f"(m0), "f"(m1));
            }

            const float* fb = feats + (size_t)b * T * KSTATES + lane;
            const int E     = (t0 + CHUNK < len) ? (t0 + CHUNK) : len;
            const int lenm1 = len - 1;

            float e;
            int   off = 0;
            float nu_in_log;

            if (c == 0) {
                // exact init: t=0 peeled
                e = __expf(trans[lane * KSTATES + START_IDX] + fb[0]);
                crf_store_e(eaddr, lane, e);
                nu_in_log = 0.0f;
                crf_run(Mp, eaddr, lane, fb, 1, E - 1, lenm1, e, off);
            } else {
                // warm-up from uniform direction (Hilbert contraction)
                e = (lane < 30) ? 1.0f : 0.0f;
                crf_store_e(eaddr, lane, e);
                crf_run(Mp, eaddr, lane, fb, t0 - WARM, WARM, lenm1, e, off);
                nu_in_log = __logf(warp_sum(e));
                off = 0;
                crf_run(Mp, eaddr, lane, fb, t0, E - t0, lenm1, e, off);
            }

            float endlog;
            if (E == len) {
                // final: log( exp(trans[STOP,:]) . e )  (lane 31 = STOP row)
                float sfin  = crf_dot_smem(Mp, eaddr);
                float sstop = __shfl_sync(FULLMASK, sfin, STOP_IDX);
                endlog = __logf(sstop);
            } else {
                endlog = __logf(warp_sum(e));
            }
            if (lane == 0)
                g_chunk[id] = (float)off * LN2 + endlog - nu_in_log;
        }

        // ---------- gold score: last-chunk warp of each batch ----------
        if (c == nch - 1) {
            const int* tb = tags + (size_t)b * T;
            const float* fbase = feats + (size_t)b * T * KSTATES;
            float g = 0.0f;
            for (int t = lane; t < len; t += 32) {
                int tg    = tb[t];
                int tprev = (t == 0) ? START_IDX : tb[t - 1];
                g += fbase[(size_t)t * KSTATES + tg] + trans[tg * KSTATES + tprev];
            }
            g = warp_sum(g);
            if (lane == 0)
                g_gold[b] = g + trans[STOP_IDX * KSTATES + tb[len - 1]];
        }
    }

    // ---- fused mean: last block reduces everything deterministically ----
    __shared__ unsigned sh_last;
    __syncthreads();
    if (tid == 0) {
        __threadfence();
        unsigned old = atomicAdd(&g_count, 1u);
        sh_last = (old == gridDim.x - 1) ? 1u : 0u;
    }
    __syncthreads();
    if (sh_last && wid == 0) {
        __threadfence();
        float v = 0.0f;
        for (int i = lane; i < B * nch; i += 32)   // fixed order -> deterministic
            v += g_chunk[i];
        for (int i = lane; i < B; i += 32)
            v -= g_gold[i];
        v = warp_sum(v);
        if (lane == 0) {
            out[0] = v / (float)B;
            g_count = 0;                           // reset for next graph replay
        }
    }
}

extern "C" void kernel_launch(void* const* d_in, const int* in_sizes, int n_in,
                              void* d_out, int out_size)
{
    const float* feats = (const float*)d_in[0];   // [B,T,K] f32
    const float* trans = (const float*)d_in[1];   // [K,K]   f32
    const int*   tags  = (const int*)  d_in[2];   // [B,T]   i32
    const int*   lens  = (const int*)  d_in[3];   // [B]     i32

    int B = in_sizes[3];
    int T = in_sizes[2] / B;

    int nch    = (T + CHUNK - 1) / CHUNK;         // chunks per sequence
    int blocks = (B * nch + 3) / 4;               // 4 chunk-warps per block

    crf_kernel<<<blocks, 128>>>(feats, trans, tags, lens,
                                (float*)d_out, B, T, nch);
}